// round 9
// baseline (speedup 1.0000x reference)
#include <cuda_runtime.h>
#include <cuda_bf16.h>
#include <cstddef>

// RandCropResize: R7 pipeline (tap tables, fused y-lerp staging, double
// buffer, 2 rows per group, one barrier per group) with a 2-pixel-per-thread
// main phase: thread t -> (row = t>>8, pixel pair = t&255). Pair-packed x-tap
// table (one int4 per pair, loaded once per block), 3 STG.64 instead of
// 6 STG.32 per group, streaming stores.

#define IMG_H 512
#define IMG_W 512
#define IMG_C 3
#define RPI   2               // rows per pipeline iteration
#define NITER 8               // iterations per block -> 16 rows/block
#define SPITCH 520            // smem row pitch (floats), float4-aligned

__device__ int4 g_xtab[64 * (IMG_W / 2)];   // per pixel pair: {l0a|l1a<<16, wxa, l0b|l1b<<16, wxb}
__device__ int2 g_ytab[64 * IMG_H];

__device__ __forceinline__ void x_taps(int w, int X1, int X2, int xlo,
                                       int& packed, float& wx)
{
    const int   ncx = X2 - X1;
    const float nx  = (float)ncx;
    float sx = ((float)w + 0.5f) * nx * (1.0f / (float)IMG_W) - 0.5f;
    sx = fminf(fmaxf(sx, 0.0f), nx - 1.0f);
    const int ix0 = (int)floorf(sx);
    const int ix1 = min(ix0 + 1, ncx - 1);
    wx = sx - (float)ix0;
    packed = ((X1 + ix0) - xlo) | (((X1 + ix1) - xlo) << 16);
}

__global__ void __launch_bounds__(512)
setup_tables_kernel(const int* __restrict__ y1v, const int* __restrict__ y2v,
                    const int* __restrict__ x1v, const int* __restrict__ x2v)
{
    const int b = blockIdx.x;
    const int t = threadIdx.x;

    const int Y1 = y1v[b], Y2 = y2v[b];
    const int X1 = x1v[b], X2 = x2v[b];

    {   // y taps for h = t (absolute source rows)
        const int   ncy = Y2 - Y1;
        const float ny  = (float)ncy;
        float sy = ((float)t + 0.5f) * ny * (1.0f / (float)IMG_H) - 0.5f;
        sy = fminf(fmaxf(sy, 0.0f), ny - 1.0f);
        const int   iy0 = (int)floorf(sy);
        const int   iy1 = min(iy0 + 1, ncy - 1);
        const float wy  = sy - (float)iy0;
        int2 e;
        e.x = (Y1 + iy0) | ((Y1 + iy1) << 16);
        e.y = __float_as_int(wy);
        g_ytab[(b << 9) + t] = e;
    }
    if (t < (IMG_W / 2)) {     // x taps for pixel pair t
        const int xlo = X1 & ~3;
        int   pa, pb;
        float wxa, wxb;
        x_taps(2 * t,     X1, X2, xlo, pa, wxa);
        x_taps(2 * t + 1, X1, X2, xlo, pb, wxb);
        int4 e;
        e.x = pa;
        e.y = __float_as_int(wxa);
        e.z = pb;
        e.w = __float_as_int(wxb);
        g_xtab[b * (IMG_W / 2) + t] = e;
    }
}

__global__ void __launch_bounds__(512, 4)
rand_crop_resize_kernel(const float* __restrict__ img,
                        const int* __restrict__ x1v,
                        const int* __restrict__ x2v,
                        float* __restrict__ out)
{
    __shared__ float sbuf[2][RPI * IMG_C * SPITCH];   // 2 x 12.2 KB

    const int hchunk = blockIdx.x * (RPI * NITER);    // 16 rows per block
    const int b      = blockIdx.y;
    const int tid    = threadIdx.x;

    const int X1    = x1v[b];
    const int X2    = x2v[b];
    const int xlo   = X1 & ~3;
    const int span4 = (((X2 + 3) & ~3) - xlo) >> 2;   // <= 128

    const size_t img_stride = (size_t)IMG_H * IMG_W;
    const float* base = img + (size_t)b * IMG_C * img_stride;

    // main-phase identity: row within group + pixel pair, taps hoisted
    const int rmain = tid >> 8;               // 0 or 1
    const int pair  = tid & 255;
    const int4  xe  = __ldg(&g_xtab[b * (IMG_W / 2) + pair]);
    const int   l0a = xe.x & 0xFFFF;
    const int   l1a = xe.x >> 16;
    const float wxa = __int_as_float(xe.y);
    const int   l0b = xe.z & 0xFFFF;
    const int   l1b = xe.z >> 16;
    const float wxb = __int_as_float(xe.w);

    // staging role (fixed per thread)
    const int  ns     = IMG_C * span4;                // <= 384
    const bool active = tid < ns;
    const int  c      = (tid >= span4) + (tid >= 2 * span4);
    const int  xq     = tid - c * span4;
    const float* pc   = base + (size_t)c * img_stride + xlo + (xq << 2);

    // prefetch registers for one group
    float4 pv0[RPI], pv1[RPI];
    float  pwy[RPI];

    // ---- prologue: load group 0 ----
#pragma unroll
    for (int r = 0; r < RPI; r++) {
        const int2 ye = __ldg(&g_ytab[(b << 9) + hchunk + r]);
        pwy[r] = __int_as_float(ye.y);
        if (active) {
            pv0[r] = *(const float4*)(pc + (size_t)(ye.x & 0xFFFF) * IMG_W);
            pv1[r] = *(const float4*)(pc + (size_t)(ye.x >> 16)   * IMG_W);
        }
    }

    float* const oblk = out + (size_t)b * IMG_C * img_stride
                            + (size_t)(hchunk + rmain) * IMG_W + (pair << 1);

    for (int g = 0; g < NITER; g++) {
        const int p = g & 1;

        // ---- STS: y-lerp the prefetched rows into smem ----
        if (active) {
#pragma unroll
            for (int r = 0; r < RPI; r++) {
                float4 f;
                f.x = pv0[r].x + (pv1[r].x - pv0[r].x) * pwy[r];
                f.y = pv0[r].y + (pv1[r].y - pv0[r].y) * pwy[r];
                f.z = pv0[r].z + (pv1[r].z - pv0[r].z) * pwy[r];
                f.w = pv0[r].w + (pv1[r].w - pv0[r].w) * pwy[r];
                *(float4*)(&sbuf[p][(r * IMG_C + c) * SPITCH + (xq << 2)]) = f;
            }
        }

        // ---- prefetch group g+1 (covered by this group's main phase) ----
        if (g + 1 < NITER) {
            const int hn = hchunk + (g + 1) * RPI;
#pragma unroll
            for (int r = 0; r < RPI; r++) {
                const int2 ye = __ldg(&g_ytab[(b << 9) + hn + r]);
                pwy[r] = __int_as_float(ye.y);
                if (active) {
                    pv0[r] = *(const float4*)(pc + (size_t)(ye.x & 0xFFFF) * IMG_W);
                    pv1[r] = *(const float4*)(pc + (size_t)(ye.x >> 16)   * IMG_W);
                }
            }
        }

        __syncthreads();   // one barrier per group

        // ---- main: this thread's row, 2 pixels x 3 channels ----
        const float* sb = &sbuf[p][rmain * IMG_C * SPITCH];
        float* og = oblk + (size_t)(g * RPI) * IMG_W;
#pragma unroll
        for (int cc = 0; cc < IMG_C; cc++) {
            const float* s = sb + cc * SPITCH;
            const float f0a = s[l0a];
            const float f1a = s[l1a];
            const float f0b = s[l0b];
            const float f1b = s[l1b];
            float2 o;
            o.x = f0a + (f1a - f0a) * wxa;
            o.y = f0b + (f1b - f0b) * wxb;
            __stcs((float2*)(og + (size_t)cc * img_stride), o);
        }
    }
}

extern "C" void kernel_launch(void* const* d_in, const int* in_sizes, int n_in,
                              void* d_out, int out_size)
{
    const float* img = (const float*)d_in[0];
    const int*   y1  = (const int*)d_in[1];
    const int*   y2  = (const int*)d_in[2];
    const int*   x1  = (const int*)d_in[3];
    const int*   x2  = (const int*)d_in[4];
    float*       out = (float*)d_out;

    setup_tables_kernel<<<64, 512>>>(y1, y2, x1, x2);

    dim3 grid(IMG_H / (RPI * NITER), 64);   // (row chunk, b) = (32, 64)
    dim3 block(512);
    rand_crop_resize_kernel<<<grid, block>>>(img, x1, x2, out);
}

// round 11
// speedup vs baseline: 1.6519x; 1.6519x over previous
#include <cuda_runtime.h>
#include <cuda_bf16.h>
#include <cstddef>

// RandCropResize: R7 pipeline + windowed staging.
// Per 2-row group, the needed source rows span at most 3 consecutive rows
// (upsample: row step <= 1). Load only that window (1-3 predicated LDG.128
// per thread, block-uniform count), then build each output row's tap pair
// from the window registers with uniform selects. Main phase unchanged from
// R7: 1 pixel/thread, stride-1 conflict-free LDS, plain coalesced STG.32.

#define IMG_H 512
#define IMG_W 512
#define IMG_C 3
#define RPI   2               // rows per pipeline iteration
#define NITER 8               // iterations per block -> 16 rows/block
#define SPITCH 520            // smem row pitch (floats), float4-aligned

__device__ int2 g_xtab[64 * IMG_W];
__device__ int2 g_ytab[64 * IMG_H];

__global__ void __launch_bounds__(512)
setup_tables_kernel(const int* __restrict__ y1v, const int* __restrict__ y2v,
                    const int* __restrict__ x1v, const int* __restrict__ x2v)
{
    const int b = blockIdx.x;
    const int t = threadIdx.x;

    const int Y1 = y1v[b], Y2 = y2v[b];
    const int X1 = x1v[b], X2 = x2v[b];

    {   // y taps for h = t (absolute source rows)
        const int   ncy = Y2 - Y1;
        const float ny  = (float)ncy;
        float sy = ((float)t + 0.5f) * ny * (1.0f / (float)IMG_H) - 0.5f;
        sy = fminf(fmaxf(sy, 0.0f), ny - 1.0f);
        const int   iy0 = (int)floorf(sy);
        const int   iy1 = min(iy0 + 1, ncy - 1);
        const float wy  = sy - (float)iy0;
        int2 e;
        e.x = (Y1 + iy0) | ((Y1 + iy1) << 16);
        e.y = __float_as_int(wy);
        g_ytab[(b << 9) + t] = e;
    }
    {   // x taps for w = t (smem-relative: minus xlo)
        const int   xlo = X1 & ~3;
        const int   ncx = X2 - X1;
        const float nx  = (float)ncx;
        float sx = ((float)t + 0.5f) * nx * (1.0f / (float)IMG_W) - 0.5f;
        sx = fminf(fmaxf(sx, 0.0f), nx - 1.0f);
        const int   ix0 = (int)floorf(sx);
        const int   ix1 = min(ix0 + 1, ncx - 1);
        const float wx  = sx - (float)ix0;
        int2 e;
        e.x = ((X1 + ix0) - xlo) | (((X1 + ix1) - xlo) << 16);
        e.y = __float_as_int(wx);
        g_xtab[(b << 9) + t] = e;
    }
}

__device__ __forceinline__ float4 lerp4(float4 a, float4 b, float w)
{
    float4 f;
    f.x = a.x + (b.x - a.x) * w;
    f.y = a.y + (b.y - a.y) * w;
    f.z = a.z + (b.z - a.z) * w;
    f.w = a.w + (b.w - a.w) * w;
    return f;
}

__global__ void __launch_bounds__(512, 4)
rand_crop_resize_kernel(const float* __restrict__ img,
                        const int* __restrict__ x1v,
                        const int* __restrict__ x2v,
                        float* __restrict__ out)
{
    __shared__ float sbuf[2][RPI * IMG_C * SPITCH];   // 2 x 12.2 KB

    const int hchunk = blockIdx.x * (RPI * NITER);    // 16 rows per block
    const int b      = blockIdx.y;
    const int tid    = threadIdx.x;

    const int X1    = x1v[b];
    const int X2    = x2v[b];
    const int xlo   = X1 & ~3;
    const int span4 = (((X2 + 3) & ~3) - xlo) >> 2;   // <= 128

    const size_t img_stride = (size_t)IMG_H * IMG_W;
    const float* base = img + (size_t)b * IMG_C * img_stride;

    // x taps: once per thread, reused for all rows
    const int2  xe = __ldg(&g_xtab[(b << 9) + tid]);
    const int   l0 = xe.x & 0xFFFF;
    const int   l1 = xe.x >> 16;
    const float wx = __int_as_float(xe.y);

    // staging role (fixed per thread)
    const int  ns     = IMG_C * span4;                // <= 384
    const bool active = tid < ns;
    const int  c      = (tid >= span4) + (tid >= 2 * span4);
    const int  xq     = tid - c * span4;
    const float* pc   = base + (size_t)c * img_stride + xlo + (xq << 2);

    // window state for one group: rows base .. base+d3 (d3 <= 2)
    float4 v0, v1, v2;
    int    d1, d2, d3;
    float  wy0, wy1;

    // ---- prologue: load window for group 0 ----
    {
        const int2 ye0 = __ldg(&g_ytab[(b << 9) + hchunk]);
        const int2 ye1 = __ldg(&g_ytab[(b << 9) + hchunk + 1]);
        const int  rb  = ye0.x & 0xFFFF;
        d1  = (ye0.x >> 16) - rb;
        d2  = (ye1.x & 0xFFFF) - rb;
        d3  = (ye1.x >> 16) - rb;
        wy0 = __int_as_float(ye0.y);
        wy1 = __int_as_float(ye1.y);
        v0 = v1 = v2 = make_float4(0.f, 0.f, 0.f, 0.f);
        if (active) {
            v0 = *(const float4*)(pc + (size_t)rb * IMG_W);
            if (d3 >= 1) v1 = *(const float4*)(pc + (size_t)(rb + 1) * IMG_W);
            if (d3 >= 2) v2 = *(const float4*)(pc + (size_t)(rb + 2) * IMG_W);
        }
    }

    float* const oblk = out + (size_t)b * IMG_C * img_stride
                            + (size_t)hchunk * IMG_W + tid;

    for (int g = 0; g < NITER; g++) {
        const int p = g & 1;

        // ---- STS: y-lerp the two output rows from the window ----
        if (active) {
            // row 0: taps v[0], v[d1]
            const float4 r0b = d1 ? v1 : v0;
            *(float4*)(&sbuf[p][(0 * IMG_C + c) * SPITCH + (xq << 2)]) =
                lerp4(v0, r0b, wy0);
            // row 1: taps v[d2], v[d3]
            const float4 r1a = d2 ? v1 : v0;
            const float4 r1b = (d3 == 0) ? v0 : ((d3 == 1) ? v1 : v2);
            *(float4*)(&sbuf[p][(1 * IMG_C + c) * SPITCH + (xq << 2)]) =
                lerp4(r1a, r1b, wy1);
        }

        // ---- prefetch window for group g+1 ----
        if (g + 1 < NITER) {
            const int  hn  = hchunk + (g + 1) * RPI;
            const int2 ye0 = __ldg(&g_ytab[(b << 9) + hn]);
            const int2 ye1 = __ldg(&g_ytab[(b << 9) + hn + 1]);
            const int  rb  = ye0.x & 0xFFFF;
            d1  = (ye0.x >> 16) - rb;
            d2  = (ye1.x & 0xFFFF) - rb;
            d3  = (ye1.x >> 16) - rb;
            wy0 = __int_as_float(ye0.y);
            wy1 = __int_as_float(ye1.y);
            if (active) {
                v0 = *(const float4*)(pc + (size_t)rb * IMG_W);
                if (d3 >= 1) v1 = *(const float4*)(pc + (size_t)(rb + 1) * IMG_W);
                if (d3 >= 2) v2 = *(const float4*)(pc + (size_t)(rb + 2) * IMG_W);
            }
        }

        __syncthreads();   // one barrier per group

        // ---- main: horizontal lerp, 2 LDS + 2 FFMA + 1 STG per output ----
        float* og = oblk + (size_t)(g * RPI) * IMG_W;
#pragma unroll
        for (int r = 0; r < RPI; r++) {
#pragma unroll
            for (int cc = 0; cc < IMG_C; cc++) {
                const float f0 = sbuf[p][(r * IMG_C + cc) * SPITCH + l0];
                const float f1 = sbuf[p][(r * IMG_C + cc) * SPITCH + l1];
                og[(size_t)cc * img_stride + (size_t)r * IMG_W] =
                    f0 + (f1 - f0) * wx;
            }
        }
    }
}

extern "C" void kernel_launch(void* const* d_in, const int* in_sizes, int n_in,
                              void* d_out, int out_size)
{
    const float* img = (const float*)d_in[0];
    const int*   y1  = (const int*)d_in[1];
    const int*   y2  = (const int*)d_in[2];
    const int*   x1  = (const int*)d_in[3];
    const int*   x2  = (const int*)d_in[4];
    float*       out = (float*)d_out;

    setup_tables_kernel<<<64, 512>>>(y1, y2, x1, x2);

    dim3 grid(IMG_H / (RPI * NITER), 64);   // (row chunk, b) = (32, 64)
    dim3 block(512);
    rand_crop_resize_kernel<<<grid, block>>>(img, x1, x2, out);
}